// round 4
// baseline (speedup 1.0000x reference)
#include <cuda_runtime.h>
#include <cuda_bf16.h>

#define BATCH 4096
#define DIM   1024
#define NS    64
#define LBLK  11
#define NBLK  93          // 93*11 = 1023
#define NCODE 2048

// ---- device-global scratch (static; no runtime alloc) ----
__device__ float  g_T[NS * NS];
__device__ float  g_E0[NS], g_E1[NS], g_Pi[NS];
__device__ float  g_L1[2 * NS * NS];
__device__ float  g_L2[4 * NS * NS];
__device__ float  g_L4[16 * NS * NS];
__device__ float  g_L8[256 * NS * NS];
__device__ float  g_L10[1024 * NS * NS];
__device__ int    g_e1[2], g_e2[4], g_e4[16], g_e8[256], g_e10[1024], g_e11[NCODE];
__device__ __nv_bfloat16 g_Pt[NCODE * NS * NS];   // transposed: Pt[c][o][k]
__device__ unsigned short g_codes[BATCH * NBLK];
__device__ double g_acc;

// ---- prep1: softmax normalization ----
__global__ void prep1_kernel(const float* __restrict__ Tr,
                             const float* __restrict__ Em,
                             const float* __restrict__ Pi) {
    int s = threadIdx.x;
    if (s == 0) g_acc = 0.0;
    if (s >= NS) return;

    float m = -1e30f;
    for (int j = 0; j < NS; j++) m = fmaxf(m, Tr[s * NS + j]);
    float sum = 0.f;
    for (int j = 0; j < NS; j++) sum += expf(Tr[s * NS + j] - m);
    float inv = 1.f / sum;
    for (int j = 0; j < NS; j++) g_T[s * NS + j] = expf(Tr[s * NS + j] - m) * inv;

    float a = Em[s * 2 + 0], b = Em[s * 2 + 1];
    float mm = fmaxf(a, b);
    float ea = expf(a - mm), eb = expf(b - mm);
    float is = 1.f / (ea + eb);
    g_E0[s] = ea * is;
    g_E1[s] = eb * is;

    float mp = -1e30f;
    for (int j = 0; j < NS; j++) mp = fmaxf(mp, Pi[j]);
    float sp = 0.f;
    for (int j = 0; j < NS; j++) sp += expf(Pi[j] - mp);
    g_Pi[s] = expf(Pi[s] - mp) / sp;
}

// ---- level1: M_y[k][o] = T[k][o] * E_y[o], normalized (max entry -> [1,2)) ----
__global__ void level1_kernel() {
    __shared__ float red[NS];
    const int yb = blockIdx.x;   // 0 or 1
    const int o  = threadIdx.x;
    const float eo = yb ? g_E1[o] : g_E0[o];

    float mx = 0.f;
    for (int k = 0; k < NS; k++) {
        float v = g_T[k * NS + o] * eo;
        g_L1[yb * NS * NS + k * NS + o] = v;
        mx = fmaxf(mx, v);
    }
    red[o] = mx;
    __syncthreads();
    for (int off = 32; off > 0; off >>= 1) {
        if (o < off) red[o] = fmaxf(red[o], red[o + off]);
        __syncthreads();
    }
    const int e = (__float_as_int(red[0]) >> 23) - 127;
    const float sc = __int_as_float((127 - e) << 23);
    for (int k = 0; k < NS; k++)
        g_L1[yb * NS * NS + k * NS + o] *= sc;
    if (o == 0) g_e1[yb] = e;
}

// ---- combine: C_c = A_a @ B_b, normalized; stage 4 writes bf16 transposed ----
__global__ void combine_kernel(int stage) {
    __shared__ float As[NS * NS];
    __shared__ float Bs[NS * NS];
    __shared__ float red[128];

    const float *A, *B; float *C;
    const int *eA, *eB; int *eC;
    int bitsB; bool fin = false;
    switch (stage) {
        case 0:  A=g_L1;  eA=g_e1;  B=g_L1; eB=g_e1; C=g_L2;  eC=g_e2;  bitsB=1; break;
        case 1:  A=g_L2;  eA=g_e2;  B=g_L2; eB=g_e2; C=g_L4;  eC=g_e4;  bitsB=2; break;
        case 2:  A=g_L4;  eA=g_e4;  B=g_L4; eB=g_e4; C=g_L8;  eC=g_e8;  bitsB=4; break;
        case 3:  A=g_L8;  eA=g_e8;  B=g_L2; eB=g_e2; C=g_L10; eC=g_e10; bitsB=2; break;
        default: A=g_L10; eA=g_e10; B=g_L1; eB=g_e1; C=nullptr; eC=g_e11; bitsB=1; fin=true; break;
    }
    const int c = blockIdx.x;
    const int a = c >> bitsB;
    const int b = c & ((1 << bitsB) - 1);
    const int tid = threadIdx.x;

    { // stage tiles into smem (float4 coalesced)
        const float4* Ag = (const float4*)(A + a * NS * NS);
        const float4* Bg = (const float4*)(B + b * NS * NS);
        float4* As4 = (float4*)As; float4* Bs4 = (float4*)Bs;
        for (int i = tid; i < NS * NS / 4; i += 128) { As4[i] = Ag[i]; Bs4[i] = Bg[i]; }
    }
    __syncthreads();

    const int j = tid & 63;        // output column
    const int h = tid >> 6;        // row half
    float out[32];
    float mx = 0.f;
#pragma unroll
    for (int ii = 0; ii < 8; ii++) {
        const int r0 = h * 32 + ii, r1 = r0 + 8, r2 = r0 + 16, r3 = r0 + 24;
        float a0 = 0.f, a1 = 0.f, a2 = 0.f, a3 = 0.f;
        for (int k = 0; k < NS; k++) {
            const float bv = Bs[k * NS + j];
            a0 = fmaf(As[r0 * NS + k], bv, a0);
            a1 = fmaf(As[r1 * NS + k], bv, a1);
            a2 = fmaf(As[r2 * NS + k], bv, a2);
            a3 = fmaf(As[r3 * NS + k], bv, a3);
        }
        out[ii] = a0; out[ii + 8] = a1; out[ii + 16] = a2; out[ii + 24] = a3;
        mx = fmaxf(fmaxf(fmaxf(a0, a1), fmaxf(a2, a3)), mx);
    }
    red[tid] = mx;
    __syncthreads();
    for (int off = 64; off > 0; off >>= 1) {
        if (tid < off) red[tid] = fmaxf(red[tid], red[tid + off]);
        __syncthreads();
    }
    const int e = (__float_as_int(red[0]) >> 23) - 127;
    const float sc = __int_as_float((127 - e) << 23);

    if (!fin) {
#pragma unroll
        for (int ii = 0; ii < 32; ii++) {
            const int r = h * 32 + ((ii & 7)) + (ii >> 3) * 8;
            C[c * NS * NS + r * NS + j] = out[ii] * sc;
        }
    } else {
#pragma unroll
        for (int ii = 0; ii < 32; ii++) {
            const int r = h * 32 + ((ii & 7)) + (ii >> 3) * 8;
            g_Pt[c * NS * NS + j * NS + r] = __float2bfloat16_rn(out[ii] * sc);
        }
    }
    if (tid == 0) eC[c] = eA[a] + eB[b] + e;
}

// ---- codes: pack 11 observations per block, MSB = earliest ----
__global__ void codes_kernel(const int* __restrict__ y) {
    __shared__ int sy[DIM];
    const int b = blockIdx.x;
    for (int t = threadIdx.x; t < DIM; t += 128) sy[t] = y[b * DIM + t];
    __syncthreads();
    const int t = threadIdx.x;
    if (t < NBLK) {
        const int base = 1 + t * LBLK;
        unsigned code = 0;
#pragma unroll
        for (int i = 0; i < LBLK; i++) code = (code << 1) | (unsigned)sy[base + i];
        g_codes[b * NBLK + t] = (unsigned short)code;
    }
}

// ---- main: one warp per element; 93 table matvecs ----
#define BF2F_LO(w) __uint_as_float((w) << 16)
#define BF2F_HI(w) __uint_as_float((w) & 0xffff0000u)
#define QSTEP(mq, aA, aB, A0, A1, A2, A3)                           \
    A0 = fmaf(aA.x, BF2F_LO(mq.x), A0);                             \
    A1 = fmaf(aA.y, BF2F_HI(mq.x), A1);                             \
    A2 = fmaf(aA.z, BF2F_LO(mq.y), A2);                             \
    A3 = fmaf(aA.w, BF2F_HI(mq.y), A3);                             \
    A0 = fmaf(aB.x, BF2F_LO(mq.z), A0);                             \
    A1 = fmaf(aB.y, BF2F_HI(mq.z), A1);                             \
    A2 = fmaf(aB.z, BF2F_LO(mq.w), A2);                             \
    A3 = fmaf(aB.w, BF2F_HI(mq.w), A3);

__global__ void __launch_bounds__(128, 6)
hmm_main_kernel(const int* __restrict__ y) {
    __shared__ __align__(16) float s_alpha[4][2][NS];

    const int tid  = threadIdx.x;
    const int lane = tid & 31;
    const int wid  = tid >> 5;
    const int b    = blockIdx.x * 4 + wid;

    // alpha_0
    const int y0 = y[b * DIM];
    float s_lo = g_Pi[lane]      * (y0 ? g_E1[lane]      : g_E0[lane]);
    float s_hi = g_Pi[lane + 32] * (y0 ? g_E1[lane + 32] : g_E0[lane + 32]);
    s_alpha[wid][0][lane]      = s_lo;
    s_alpha[wid][0][lane + 32] = s_hi;
    __syncwarp();

    const unsigned short* __restrict__ crow = g_codes + b * NBLK;
    int ce = 0;
    int p  = 0;

    for (int j = 0; j < NBLK; j++) {
        const int code = crow[j];
        const uint4* __restrict__ c0 =
            (const uint4*)(g_Pt + (size_t)code * NS * NS + lane * NS);
        const uint4* __restrict__ c1 =
            (const uint4*)(g_Pt + (size_t)code * NS * NS + (lane + 32) * NS);
        const float4* __restrict__ As4 = (const float4*)s_alpha[wid][p];

        int e_in = (__float_as_int(s_alpha[wid][p][0]) >> 23) - 127;
        e_in = max(-126, min(126, e_in));
        const float rsc = __int_as_float((127 - e_in) << 23);

        float a00 = 0.f, a01 = 0.f, a02 = 0.f, a03 = 0.f;
        float a10 = 0.f, a11 = 0.f, a12 = 0.f, a13 = 0.f;

        {   // k = 0..31
            uint4 m0[4], m1[4];
#pragma unroll
            for (int q = 0; q < 4; q++) { m0[q] = c0[q]; m1[q] = c1[q]; }
#pragma unroll
            for (int q = 0; q < 4; q++) {
                const float4 aA = As4[2 * q], aB = As4[2 * q + 1];
                QSTEP(m0[q], aA, aB, a00, a01, a02, a03)
                QSTEP(m1[q], aA, aB, a10, a11, a12, a13)
            }
        }
        {   // k = 32..63
            uint4 m0[4], m1[4];
#pragma unroll
            for (int q = 0; q < 4; q++) { m0[q] = c0[q + 4]; m1[q] = c1[q + 4]; }
#pragma unroll
            for (int q = 0; q < 4; q++) {
                const float4 aA = As4[2 * q + 8], aB = As4[2 * q + 9];
                QSTEP(m0[q], aA, aB, a00, a01, a02, a03)
                QSTEP(m1[q], aA, aB, a10, a11, a12, a13)
            }
        }

        s_lo = ((a00 + a01) + (a02 + a03)) * rsc;
        s_hi = ((a10 + a11) + (a12 + a13)) * rsc;
        ce  += e_in + g_e11[code];

        __syncwarp();
        p ^= 1;
        s_alpha[wid][p][lane]      = s_lo;
        s_alpha[wid][p][lane + 32] = s_hi;
        __syncwarp();
    }

    // log(sum alpha) + ce*ln2
    float v = s_lo + s_hi;
#pragma unroll
    for (int off = 16; off > 0; off >>= 1)
        v += __shfl_xor_sync(0xffffffffu, v, off);

    if (lane == 0) {
        const double logp = (double)logf(v) + (double)ce * 0.6931471805599453;
        atomicAdd(&g_acc, logp);
    }
}

__global__ void fin_kernel(float* out) {
    out[0] = (float)(g_acc * (1.0 / 4096.0));
}

extern "C" void kernel_launch(void* const* d_in, const int* in_sizes, int n_in,
                              void* d_out, int out_size) {
    const int*   y  = (const int*)  d_in[0];
    const float* Tr = (const float*)d_in[1];
    const float* Em = (const float*)d_in[2];
    const float* Pi = (const float*)d_in[3];

    prep1_kernel<<<1, 64>>>(Tr, Em, Pi);
    level1_kernel<<<2, 64>>>();
    combine_kernel<<<4, 128>>>(0);      // L2
    combine_kernel<<<16, 128>>>(1);     // L4
    combine_kernel<<<256, 128>>>(2);    // L8
    combine_kernel<<<1024, 128>>>(3);   // L10
    combine_kernel<<<2048, 128>>>(4);   // L11 -> bf16 transposed table
    codes_kernel<<<BATCH, 128>>>(y);
    hmm_main_kernel<<<BATCH / 4, 128>>>(y);
    fin_kernel<<<1, 1>>>((float*)d_out);
}

// round 5
// speedup vs baseline: 2.8222x; 2.8222x over previous
#include <cuda_runtime.h>
#include <cuda_bf16.h>

#define BATCH 4096
#define DIM   1024
#define NS    64
#define LBLK  11
#define NBLK  93          // 93*11 = 1023
#define NCODE 2048

// ---- device-global scratch (static; no runtime alloc) ----
__device__ float  g_T[NS * NS];
__device__ float  g_E0[NS], g_E1[NS], g_Pi[NS];
__device__ float  g_L1[2 * NS * NS];
__device__ float  g_L2[4 * NS * NS];
__device__ float  g_L4[16 * NS * NS];
__device__ float  g_L8[256 * NS * NS];
__device__ float  g_L10[1024 * NS * NS];
__device__ int    g_e1[2], g_e2[4], g_e4[16], g_e8[256], g_e10[1024], g_e11[NCODE];
// Permuted bf16x2 table: u32 word (M[2kk][o] lo | M[2kk+1][o] hi) at
// idx(o,kk) = (kk>>1)*128 + (o&31)*4 + ((o>>5)<<1) + (kk&1), per code (2048 u32 = 8KB)
__device__ unsigned g_Pt[NCODE * 2048];
__device__ unsigned short g_codes[BATCH * NBLK];
__device__ double g_acc;

__device__ __forceinline__ unsigned bf16r(float f) {   // rn bf16 bits
    unsigned u = __float_as_uint(f);
    return (u + 0x7fffu + ((u >> 16) & 1u)) >> 16;
}

// ---- prep1: softmax normalization ----
__global__ void prep1_kernel(const float* __restrict__ Tr,
                             const float* __restrict__ Em,
                             const float* __restrict__ Pi) {
    int s = threadIdx.x;
    if (s == 0) g_acc = 0.0;
    if (s >= NS) return;

    float m = -1e30f;
    for (int j = 0; j < NS; j++) m = fmaxf(m, Tr[s * NS + j]);
    float sum = 0.f;
    for (int j = 0; j < NS; j++) sum += expf(Tr[s * NS + j] - m);
    float inv = 1.f / sum;
    for (int j = 0; j < NS; j++) g_T[s * NS + j] = expf(Tr[s * NS + j] - m) * inv;

    float a = Em[s * 2 + 0], b = Em[s * 2 + 1];
    float mm = fmaxf(a, b);
    float ea = expf(a - mm), eb = expf(b - mm);
    float is = 1.f / (ea + eb);
    g_E0[s] = ea * is;
    g_E1[s] = eb * is;

    float mp = -1e30f;
    for (int j = 0; j < NS; j++) mp = fmaxf(mp, Pi[j]);
    float sp = 0.f;
    for (int j = 0; j < NS; j++) sp += expf(Pi[j] - mp);
    g_Pi[s] = expf(Pi[s] - mp) / sp;
}

// ---- level1: M_y[k][o] = T[k][o] * E_y[o], normalized ----
__global__ void level1_kernel() {
    __shared__ float red[NS];
    const int yb = blockIdx.x;
    const int o  = threadIdx.x;
    const float eo = yb ? g_E1[o] : g_E0[o];

    float mx = 0.f;
    for (int k = 0; k < NS; k++) {
        float v = g_T[k * NS + o] * eo;
        g_L1[yb * NS * NS + k * NS + o] = v;
        mx = fmaxf(mx, v);
    }
    red[o] = mx;
    __syncthreads();
    for (int off = 32; off > 0; off >>= 1) {
        if (o < off) red[o] = fmaxf(red[o], red[o + off]);
        __syncthreads();
    }
    const int e = (__float_as_int(red[0]) >> 23) - 127;
    const float sc = __int_as_float((127 - e) << 23);
    for (int k = 0; k < NS; k++)
        g_L1[yb * NS * NS + k * NS + o] *= sc;
    if (o == 0) g_e1[yb] = e;
}

// ---- combine: C_c = A_a @ B_b, normalized; stage 4 writes permuted bf16x2 u32 ----
__global__ void combine_kernel(int stage) {
    __shared__ float As[NS * NS];
    __shared__ float Bs[NS * NS];
    __shared__ float red[128];

    const float *A, *B; float *C;
    const int *eA, *eB; int *eC;
    int bitsB; bool fin = false;
    switch (stage) {
        case 0:  A=g_L1;  eA=g_e1;  B=g_L1; eB=g_e1; C=g_L2;  eC=g_e2;  bitsB=1; break;
        case 1:  A=g_L2;  eA=g_e2;  B=g_L2; eB=g_e2; C=g_L4;  eC=g_e4;  bitsB=2; break;
        case 2:  A=g_L4;  eA=g_e4;  B=g_L4; eB=g_e4; C=g_L8;  eC=g_e8;  bitsB=4; break;
        case 3:  A=g_L8;  eA=g_e8;  B=g_L2; eB=g_e2; C=g_L10; eC=g_e10; bitsB=2; break;
        default: A=g_L10; eA=g_e10; B=g_L1; eB=g_e1; C=nullptr; eC=g_e11; bitsB=1; fin=true; break;
    }
    const int c = blockIdx.x;
    const int a = c >> bitsB;
    const int b = c & ((1 << bitsB) - 1);
    const int tid = threadIdx.x;

    {
        const float4* Ag = (const float4*)(A + a * NS * NS);
        const float4* Bg = (const float4*)(B + b * NS * NS);
        float4* As4 = (float4*)As; float4* Bs4 = (float4*)Bs;
        for (int i = tid; i < NS * NS / 4; i += 128) { As4[i] = Ag[i]; Bs4[i] = Bg[i]; }
    }
    __syncthreads();

    const int j = tid & 63;        // output column
    const int h = tid >> 6;        // row half
    float out[32];
    float mx = 0.f;
#pragma unroll
    for (int ii = 0; ii < 8; ii++) {
        const int r0 = h * 32 + ii, r1 = r0 + 8, r2 = r0 + 16, r3 = r0 + 24;
        float a0 = 0.f, a1 = 0.f, a2 = 0.f, a3 = 0.f;
        for (int k = 0; k < NS; k++) {
            const float bv = Bs[k * NS + j];
            a0 = fmaf(As[r0 * NS + k], bv, a0);
            a1 = fmaf(As[r1 * NS + k], bv, a1);
            a2 = fmaf(As[r2 * NS + k], bv, a2);
            a3 = fmaf(As[r3 * NS + k], bv, a3);
        }
        out[ii] = a0; out[ii + 8] = a1; out[ii + 16] = a2; out[ii + 24] = a3;
        mx = fmaxf(fmaxf(fmaxf(a0, a1), fmaxf(a2, a3)), mx);
    }
    red[tid] = mx;
    __syncthreads();
    for (int off = 64; off > 0; off >>= 1) {
        if (tid < off) red[tid] = fmaxf(red[tid], red[tid + off]);
        __syncthreads();
    }
    const int e = (__float_as_int(red[0]) >> 23) - 127;
    const float sc = __int_as_float((127 - e) << 23);

    if (!fin) {
#pragma unroll
        for (int ii = 0; ii < 32; ii++)     // out[ii] is row h*32+ii (identity map)
            C[c * NS * NS + (h * 32 + ii) * NS + j] = out[ii] * sc;
    } else {
        // permuted bf16x2 write: thread holds rows h*32 .. h*32+31 of column j
        unsigned* dst = g_Pt + c * 2048;
#pragma unroll
        for (int m = 0; m < 16; m++) {
            const unsigned lo = bf16r(out[2 * m] * sc);
            const unsigned hi = bf16r(out[2 * m + 1] * sc);
            const int kk  = h * 16 + m;
            const int idx = (kk >> 1) * 128 + (j & 31) * 4 + ((j >> 5) << 1) + (kk & 1);
            dst[idx] = lo | (hi << 16);
        }
    }
    if (tid == 0) eC[c] = eA[a] + eB[b] + e;
}

// ---- codes: pack 11 observations per block, MSB = earliest ----
__global__ void codes_kernel(const int* __restrict__ y) {
    __shared__ int sy[DIM];
    const int b = blockIdx.x;
    for (int t = threadIdx.x; t < DIM; t += 128) sy[t] = y[b * DIM + t];
    __syncthreads();
    const int t = threadIdx.x;
    if (t < NBLK) {
        const int base = 1 + t * LBLK;
        unsigned code = 0;
#pragma unroll
        for (int i = 0; i < LBLK; i++) code = (code << 1) | (unsigned)sy[base + i];
        g_codes[b * NBLK + t] = (unsigned short)code;
    }
}

// ---- main: one warp per element; coalesced prefetched table matvecs ----
#define PREFETCH(MB, c)                                                       \
    {                                                                         \
        const uint4* __restrict__ tp = tbl + (size_t)(c) * 512 + lane;        \
        _Pragma("unroll")                                                     \
        for (int i = 0; i < 16; i++) MB[i] = tp[i * 32];                      \
    }

#define COMPUTE(MB, CODE)                                                     \
    {                                                                         \
        int e_in = (__float_as_int(s_alpha[wid][p][0]) >> 23) - 127;          \
        e_in = max(-126, min(126, e_in));                                     \
        const float rsc = __int_as_float((127 - e_in) << 23);                 \
        const float4* __restrict__ As4 = (const float4*)s_alpha[wid][p];      \
        float a0=0.f,a1=0.f,a2=0.f,a3=0.f,b0=0.f,b1=0.f,b2=0.f,b3=0.f;        \
        _Pragma("unroll")                                                     \
        for (int i = 0; i < 16; i++) {                                        \
            const float4 aa = As4[i];                                         \
            const uint4  u  = MB[i];                                          \
            a0 = fmaf(__uint_as_float(u.x << 16),          aa.x, a0);         \
            a1 = fmaf(__uint_as_float(u.x & 0xffff0000u),  aa.y, a1);         \
            a2 = fmaf(__uint_as_float(u.y << 16),          aa.z, a2);         \
            a3 = fmaf(__uint_as_float(u.y & 0xffff0000u),  aa.w, a3);         \
            b0 = fmaf(__uint_as_float(u.z << 16),          aa.x, b0);         \
            b1 = fmaf(__uint_as_float(u.z & 0xffff0000u),  aa.y, b1);         \
            b2 = fmaf(__uint_as_float(u.w << 16),          aa.z, b2);         \
            b3 = fmaf(__uint_as_float(u.w & 0xffff0000u),  aa.w, b3);         \
        }                                                                     \
        const float s_lo = ((a0 + a1) + (a2 + a3)) * rsc;                     \
        const float s_hi = ((b0 + b1) + (b2 + b3)) * rsc;                     \
        ce += e_in + g_e11[CODE];                                             \
        __syncwarp();                                                         \
        p ^= 1;                                                               \
        s_alpha[wid][p][lane]      = s_lo;                                    \
        s_alpha[wid][p][lane + 32] = s_hi;                                    \
        __syncwarp();                                                         \
    }

__global__ void __launch_bounds__(128)
hmm_main_kernel(const int* __restrict__ y) {
    __shared__ __align__(16) float s_alpha[4][2][NS];

    const int tid  = threadIdx.x;
    const int lane = tid & 31;
    const int wid  = tid >> 5;
    const int b    = blockIdx.x * 4 + wid;

    const int y0 = y[b * DIM];
    s_alpha[wid][0][lane]      = g_Pi[lane]      * (y0 ? g_E1[lane]      : g_E0[lane]);
    s_alpha[wid][0][lane + 32] = g_Pi[lane + 32] * (y0 ? g_E1[lane + 32] : g_E0[lane + 32]);
    __syncwarp();

    const unsigned short* __restrict__ crow = g_codes + b * NBLK;
    const uint4* __restrict__ tbl = (const uint4*)g_Pt;

    uint4 mA[16], mB[16];
    int ce = 0, p = 0;

    int cA = crow[0], cB;
    PREFETCH(mA, cA)

    for (int jj = 0; jj < 92; jj += 2) {
        cB = crow[jj + 1];
        PREFETCH(mB, cB)
        COMPUTE(mA, cA)
        cA = crow[jj + 2];
        PREFETCH(mA, cA)
        COMPUTE(mB, cB)
    }
    COMPUTE(mA, cA)   // j = 92 (cA = crow[92], prefetched at jj = 90)

    // log(sum alpha) + ce*ln2
    float v = s_alpha[wid][p][lane] + s_alpha[wid][p][lane + 32];
#pragma unroll
    for (int off = 16; off > 0; off >>= 1)
        v += __shfl_xor_sync(0xffffffffu, v, off);

    if (lane == 0) {
        const double logp = (double)logf(v) + (double)ce * 0.6931471805599453;
        atomicAdd(&g_acc, logp);
    }
}

__global__ void fin_kernel(float* out) {
    out[0] = (float)(g_acc * (1.0 / 4096.0));
}

extern "C" void kernel_launch(void* const* d_in, const int* in_sizes, int n_in,
                              void* d_out, int out_size) {
    const int*   y  = (const int*)  d_in[0];
    const float* Tr = (const float*)d_in[1];
    const float* Em = (const float*)d_in[2];
    const float* Pi = (const float*)d_in[3];

    prep1_kernel<<<1, 64>>>(Tr, Em, Pi);
    level1_kernel<<<2, 64>>>();
    combine_kernel<<<4, 128>>>(0);      // L2
    combine_kernel<<<16, 128>>>(1);     // L4
    combine_kernel<<<256, 128>>>(2);    // L8
    combine_kernel<<<1024, 128>>>(3);   // L10
    combine_kernel<<<2048, 128>>>(4);   // L11 -> permuted bf16x2 table
    codes_kernel<<<BATCH, 128>>>(y);
    hmm_main_kernel<<<BATCH / 4, 128>>>(y);
    fin_kernel<<<1, 1>>>((float*)d_out);
}

// round 6
// speedup vs baseline: 4.1626x; 1.4749x over previous
#include <cuda_runtime.h>
#include <cuda_bf16.h>
#include <cuda_fp16.h>

#define BATCH 4096
#define DIM   1024
#define NS    64
#define LBLK  11
#define NBLK  93          // 93*11 = 1023
#define NCODE 2048

// ---- device-global scratch (static; no runtime alloc) ----
__device__ float  g_T[NS * NS];
__device__ float  g_E0[NS], g_E1[NS], g_Pi[NS];
__device__ float  g_L1[2 * NS * NS];
__device__ float  g_L2[4 * NS * NS];
__device__ float  g_L4[16 * NS * NS];
__device__ float  g_L8[256 * NS * NS];
__device__ float  g_L10[1024 * NS * NS];
__device__ int    g_e1[2], g_e2[4], g_e4[16], g_e8[256], g_e10[1024], g_e11[NCODE];
// fp8 e4m3 table, permuted: byte(c,o,k) = c*4096 + ((o<32?0:4)+(k>>4))*512 + (o&31)*16 + (k&15)
__device__ uint4  g_Pt4[NCODE * 256];    // 8 MB
__device__ unsigned short g_codes[BATCH * NBLK];
__device__ double g_acc;

// ---- fp8 helpers ----
__device__ __forceinline__ unsigned short f2_e4m3x2(float hi, float lo) {
    unsigned short r;
    asm("cvt.rn.satfinite.e4m3x2.f32 %0, %1, %2;" : "=h"(r) : "f"(hi), "f"(lo));
    return r;
}
__device__ __forceinline__ __half2 e4m3x2_h2(unsigned short s) {
    unsigned r;
    asm("cvt.rn.f16x2.e4m3x2 %0, %1;" : "=r"(r) : "h"(s));
    return *(__half2*)&r;
}
__device__ __forceinline__ __half2 as_h2(unsigned w) { return *(__half2*)&w; }

// ---- prep1: softmax normalization ----
__global__ void prep1_kernel(const float* __restrict__ Tr,
                             const float* __restrict__ Em,
                             const float* __restrict__ Pi) {
    int s = threadIdx.x;
    if (s == 0) g_acc = 0.0;
    if (s >= NS) return;

    float m = -1e30f;
    for (int j = 0; j < NS; j++) m = fmaxf(m, Tr[s * NS + j]);
    float sum = 0.f;
    for (int j = 0; j < NS; j++) sum += expf(Tr[s * NS + j] - m);
    float inv = 1.f / sum;
    for (int j = 0; j < NS; j++) g_T[s * NS + j] = expf(Tr[s * NS + j] - m) * inv;

    float a = Em[s * 2 + 0], b = Em[s * 2 + 1];
    float mm = fmaxf(a, b);
    float ea = expf(a - mm), eb = expf(b - mm);
    float is = 1.f / (ea + eb);
    g_E0[s] = ea * is;
    g_E1[s] = eb * is;

    float mp = -1e30f;
    for (int j = 0; j < NS; j++) mp = fmaxf(mp, Pi[j]);
    float sp = 0.f;
    for (int j = 0; j < NS; j++) sp += expf(Pi[j] - mp);
    g_Pi[s] = expf(Pi[s] - mp) / sp;
}

// ---- level1: M_y[k][o] = T[k][o] * E_y[o], normalized ----
__global__ void level1_kernel() {
    __shared__ float red[NS];
    const int yb = blockIdx.x;
    const int o  = threadIdx.x;
    const float eo = yb ? g_E1[o] : g_E0[o];

    float mx = 0.f;
    for (int k = 0; k < NS; k++) {
        float v = g_T[k * NS + o] * eo;
        g_L1[yb * NS * NS + k * NS + o] = v;
        mx = fmaxf(mx, v);
    }
    red[o] = mx;
    __syncthreads();
    for (int off = 32; off > 0; off >>= 1) {
        if (o < off) red[o] = fmaxf(red[o], red[o + off]);
        __syncthreads();
    }
    const int e = (__float_as_int(red[0]) >> 23) - 127;
    const float sc = __int_as_float((127 - e) << 23);
    for (int k = 0; k < NS; k++)
        g_L1[yb * NS * NS + k * NS + o] *= sc;
    if (o == 0) g_e1[yb] = e;
}

// ---- combine: C_c = A_a @ B_b, normalized; stage 4 writes permuted e4m3 ----
__global__ void combine_kernel(int stage) {
    __shared__ float As[NS * NS];
    __shared__ float Bs[NS * NS];
    __shared__ float red[128];

    const float *A, *B; float *C;
    const int *eA, *eB; int *eC;
    int bitsB; bool fin = false;
    switch (stage) {
        case 0:  A=g_L1;  eA=g_e1;  B=g_L1; eB=g_e1; C=g_L2;  eC=g_e2;  bitsB=1; break;
        case 1:  A=g_L2;  eA=g_e2;  B=g_L2; eB=g_e2; C=g_L4;  eC=g_e4;  bitsB=2; break;
        case 2:  A=g_L4;  eA=g_e4;  B=g_L4; eB=g_e4; C=g_L8;  eC=g_e8;  bitsB=4; break;
        case 3:  A=g_L8;  eA=g_e8;  B=g_L2; eB=g_e2; C=g_L10; eC=g_e10; bitsB=2; break;
        default: A=g_L10; eA=g_e10; B=g_L1; eB=g_e1; C=nullptr; eC=g_e11; bitsB=1; fin=true; break;
    }
    const int c = blockIdx.x;
    const int a = c >> bitsB;
    const int b = c & ((1 << bitsB) - 1);
    const int tid = threadIdx.x;

    {
        const float4* Ag = (const float4*)(A + a * NS * NS);
        const float4* Bg = (const float4*)(B + b * NS * NS);
        float4* As4 = (float4*)As; float4* Bs4 = (float4*)Bs;
        for (int i = tid; i < NS * NS / 4; i += 128) { As4[i] = Ag[i]; Bs4[i] = Bg[i]; }
    }
    __syncthreads();

    const int j = tid & 63;        // output column
    const int h = tid >> 6;        // row half
    float out[32];
    float mx = 0.f;
#pragma unroll
    for (int ii = 0; ii < 8; ii++) {
        const int r0 = h * 32 + ii, r1 = r0 + 8, r2 = r0 + 16, r3 = r0 + 24;
        float a0 = 0.f, a1 = 0.f, a2 = 0.f, a3 = 0.f;
#pragma unroll 16
        for (int k = 0; k < NS; k++) {
            const float bv = Bs[k * NS + j];
            a0 = fmaf(As[r0 * NS + k], bv, a0);
            a1 = fmaf(As[r1 * NS + k], bv, a1);
            a2 = fmaf(As[r2 * NS + k], bv, a2);
            a3 = fmaf(As[r3 * NS + k], bv, a3);
        }
        out[ii] = a0; out[ii + 8] = a1; out[ii + 16] = a2; out[ii + 24] = a3;
        mx = fmaxf(fmaxf(fmaxf(a0, a1), fmaxf(a2, a3)), mx);
    }
    red[tid] = mx;
    __syncthreads();
    for (int off = 64; off > 0; off >>= 1) {
        if (tid < off) red[tid] = fmaxf(red[tid], red[tid + off]);
        __syncthreads();
    }
    const int e = (__float_as_int(red[0]) >> 23) - 127;
    const float sc = __int_as_float((127 - e) << 23);

    if (!fin) {
#pragma unroll
        for (int ii = 0; ii < 32; ii++)     // out[ii] = row h*32+ii, col j
            C[c * NS * NS + (h * 32 + ii) * NS + j] = out[ii] * sc;
    } else {
        // permuted e4m3 write: thread owns rows k=h*32..h*32+31 of column j
        const int base_i = (j < 32 ? 0 : 4) + 2 * h;
#pragma unroll
        for (int ih = 0; ih < 2; ih++) {
            unsigned w[4];
#pragma unroll
            for (int q = 0; q < 4; q++) {
                const int t = ih * 16 + 4 * q;
                unsigned p01 = f2_e4m3x2(out[t + 1] * sc, out[t + 0] * sc);
                unsigned p23 = f2_e4m3x2(out[t + 3] * sc, out[t + 2] * sc);
                w[q] = p01 | (p23 << 16);
            }
            uint4* dst = (uint4*)((char*)g_Pt4 + (size_t)c * 4096
                                  + (base_i + ih) * 512 + (j & 31) * 16);
            *dst = make_uint4(w[0], w[1], w[2], w[3]);
        }
    }
    if (tid == 0) eC[c] = eA[a] + eB[b] + e;
}

// ---- codes: pack 11 observations per block, MSB = earliest ----
__global__ void codes_kernel(const int* __restrict__ y) {
    __shared__ int sy[DIM];
    const int b = blockIdx.x;
    for (int t = threadIdx.x; t < DIM; t += 128) sy[t] = y[b * DIM + t];
    __syncthreads();
    const int t = threadIdx.x;
    if (t < NBLK) {
        const int base = 1 + t * LBLK;
        unsigned code = 0;
#pragma unroll
        for (int i = 0; i < LBLK; i++) code = (code << 1) | (unsigned)sy[base + i];
        g_codes[b * NBLK + t] = (unsigned short)code;
    }
}

// ---- main: one warp per element; fp8 table, half2 matvec ----
#define PREFETCH(MB, c)                                                       \
    {                                                                         \
        const uint4* __restrict__ tp = g_Pt4 + (size_t)(c) * 256 + lane;      \
        _Pragma("unroll")                                                     \
        for (int i = 0; i < 8; i++) MB[i] = tp[i * 32];                       \
    }

// 8 hfma2: one table uint4 (16 e4m3, k-range) x two alpha uint4 (8 half2)
#define PROC8(u, av0, av1, acc)                                               \
    acc = __hfma2(e4m3x2_h2((unsigned short)(u).x),         as_h2((av0).x), acc); \
    acc = __hfma2(e4m3x2_h2((unsigned short)((u).x >> 16)), as_h2((av0).y), acc); \
    acc = __hfma2(e4m3x2_h2((unsigned short)(u).y),         as_h2((av0).z), acc); \
    acc = __hfma2(e4m3x2_h2((unsigned short)((u).y >> 16)), as_h2((av0).w), acc); \
    acc = __hfma2(e4m3x2_h2((unsigned short)(u).z),         as_h2((av1).x), acc); \
    acc = __hfma2(e4m3x2_h2((unsigned short)((u).z >> 16)), as_h2((av1).y), acc); \
    acc = __hfma2(e4m3x2_h2((unsigned short)(u).w),         as_h2((av1).z), acc); \
    acc = __hfma2(e4m3x2_h2((unsigned short)((u).w >> 16)), as_h2((av1).w), acc);

// normalize (exact 2^-e, entry-0 exponent + 2 bits headroom), pack to half2, store
#define PACKSTORE(PP)                                                         \
    {                                                                         \
        const float ev = __shfl_sync(0xffffffffu, s_lo, 0);                   \
        int e = (__float_as_int(ev) >> 23) - 125;                             \
        e = max(-120, min(120, e));                                           \
        const float rsc = __int_as_float((127 - e) << 23);                    \
        s_lo *= rsc; s_hi *= rsc; ce += e;                                    \
        const float lo0 = __shfl_sync(0xffffffffu, s_lo, (2 * lane) & 31);    \
        const float lo1 = __shfl_sync(0xffffffffu, s_lo, (2 * lane + 1) & 31);\
        const float hi0 = __shfl_sync(0xffffffffu, s_hi, (2 * lane) & 31);    \
        const float hi1 = __shfl_sync(0xffffffffu, s_hi, (2 * lane + 1) & 31);\
        const float x0 = lane < 16 ? lo0 : hi0;                               \
        const float x1 = lane < 16 ? lo1 : hi1;                               \
        s_ah[wid][PP][lane] = __floats2half2_rn(x0, x1);                      \
        __syncwarp();                                                         \
    }

#define COMPUTE(MB, CODE)                                                     \
    {                                                                         \
        const uint4* __restrict__ ah = (const uint4*)s_ah[wid][p];            \
        uint4 au[8];                                                          \
        _Pragma("unroll")                                                     \
        for (int q = 0; q < 8; q++) au[q] = ah[q];                            \
        __half2 c0 = __float2half2_rn(0.f), c1 = c0, c2 = c0, c3 = c0;        \
        __half2 d0 = c0, d1 = c0, d2 = c0, d3 = c0;                           \
        PROC8(MB[0], au[0], au[1], c0)                                        \
        PROC8(MB[1], au[2], au[3], c1)                                        \
        PROC8(MB[2], au[4], au[5], c2)                                        \
        PROC8(MB[3], au[6], au[7], c3)                                        \
        PROC8(MB[4], au[0], au[1], d0)                                        \
        PROC8(MB[5], au[2], au[3], d1)                                        \
        PROC8(MB[6], au[4], au[5], d2)                                        \
        PROC8(MB[7], au[6], au[7], d3)                                        \
        const __half2 tc = __hadd2(__hadd2(c0, c1), __hadd2(c2, c3));         \
        const __half2 td = __hadd2(__hadd2(d0, d1), __hadd2(d2, d3));         \
        s_lo = __low2float(tc) + __high2float(tc);                            \
        s_hi = __low2float(td) + __high2float(td);                            \
        ce += g_e11[CODE];                                                    \
        p ^= 1;                                                               \
        PACKSTORE(p)                                                          \
    }

__global__ void __launch_bounds__(128)
hmm_main_kernel(const int* __restrict__ y) {
    __shared__ __align__(16) __half2 s_ah[4][2][32];

    const int tid  = threadIdx.x;
    const int lane = tid & 31;
    const int wid  = tid >> 5;
    const int b    = blockIdx.x * 4 + wid;

    const int y0 = y[b * DIM];
    float s_lo = g_Pi[lane]      * (y0 ? g_E1[lane]      : g_E0[lane]);
    float s_hi = g_Pi[lane + 32] * (y0 ? g_E1[lane + 32] : g_E0[lane + 32]);

    int ce = 0, p = 0;
    PACKSTORE(0)

    const unsigned short* __restrict__ crow = g_codes + b * NBLK;
    uint4 mA[8], mB[8];

    int cA = crow[0], cB;
    PREFETCH(mA, cA)

    for (int jj = 0; jj < 92; jj += 2) {
        cB = crow[jj + 1];
        PREFETCH(mB, cB)
        COMPUTE(mA, cA)
        cA = crow[jj + 2];
        PREFETCH(mA, cA)
        COMPUTE(mB, cB)
    }
    COMPUTE(mA, cA)   // j = 92 (prefetched at jj = 90)

    // log(sum alpha) + ce*ln2
    float v = s_lo + s_hi;
#pragma unroll
    for (int off = 16; off > 0; off >>= 1)
        v += __shfl_xor_sync(0xffffffffu, v, off);

    if (lane == 0) {
        const double logp = (double)logf(v) + (double)ce * 0.6931471805599453;
        atomicAdd(&g_acc, logp);
    }
}

__global__ void fin_kernel(float* out) {
    out[0] = (float)(g_acc * (1.0 / 4096.0));
}

extern "C" void kernel_launch(void* const* d_in, const int* in_sizes, int n_in,
                              void* d_out, int out_size) {
    const int*   y  = (const int*)  d_in[0];
    const float* Tr = (const float*)d_in[1];
    const float* Em = (const float*)d_in[2];
    const float* Pi = (const float*)d_in[3];

    prep1_kernel<<<1, 64>>>(Tr, Em, Pi);
    level1_kernel<<<2, 64>>>();
    combine_kernel<<<4, 128>>>(0);      // L2
    combine_kernel<<<16, 128>>>(1);     // L4
    combine_kernel<<<256, 128>>>(2);    // L8
    combine_kernel<<<1024, 128>>>(3);   // L10
    combine_kernel<<<2048, 128>>>(4);   // L11 -> permuted e4m3 table
    codes_kernel<<<BATCH, 128>>>(y);
    hmm_main_kernel<<<BATCH / 4, 128>>>(y);
    fin_kernel<<<1, 1>>>((float*)d_out);
}